// round 13
// baseline (speedup 1.0000x reference)
#include <cuda_runtime.h>
#include <cuda_fp16.h>

#define NN 100000
#define NE 1600000
#define SCAN_B 98           // ceil(100000 / 1024); all 98 blocks co-resident

#define TILE_N 64
#define NTILES ((NN + TILE_N - 1) / TILE_N)   // 1563 (last tile partial)

// smem layout (floats) for fused GEMM kernel
#define W1T_SZ (8 * 1028)   // layer1 weights, 8 jt-regions, {wl,wr} interleaved, +4 pad
#define WPT_SZ (8 * 516)    // proj weights, 8 jtp-regions, {wl2,wr2} interleaved, +4 pad
#define AX_SZ  (64 * 130)   // 64 nodes x 64 k of {agg,x} float2, row 130 floats
#define SMEM_FLOATS (W1T_SZ + WPT_SZ + AX_SZ)
#define SMEM_BYTES  (SMEM_FLOATS * 4)         // 82688 B

// ---- scratch (static __device__ arrays; no allocation allowed) ----
__device__ int    g_is64;
__device__ int    g_cnt[NN];
__device__ int    g_flag[128];     // lookback flags (re-zeroed every launch)
__device__ int    g_agg[128];      // per-block scan aggregates
__device__ int    g_rowstart[NN + 1];
__device__ int    g_cursor[NN];
__device__ int    g_csr[NE];
__device__ __half g_xh[NN * 64];   // fp16 mirror of x (gather path only)
__device__ float  g_agg1[NN * 64];
__device__ __half g_p2h[NN * 32];  // h @ Wl2 in fp16 (gathered in final)
__device__ float  g_r2[NN * 32];   // h @ Wr2 (root term, fp32)

// ---- f32x2 packed helpers ----
__device__ __forceinline__ unsigned long long ffma2(
    unsigned long long a, unsigned long long b, unsigned long long c) {
    unsigned long long d;
    asm("fma.rn.f32x2 %0, %1, %2, %3;" : "=l"(d) : "l"(a), "l"(b), "l"(c));
    return d;
}
__device__ __forceinline__ unsigned long long pack2(float lo, float hi) {
    unsigned long long r;
    asm("mov.b64 %0, {%1, %2};" : "=l"(r) : "f"(lo), "f"(hi));
    return r;
}
__device__ __forceinline__ float2 unpack2(unsigned long long v) {
    float2 f;
    asm("mov.b64 {%0, %1}, %2;" : "=f"(f.x), "=f"(f.y) : "l"(v));
    return f;
}

// init: detect int64 vs int32 edge_index (block 0 warp 0), zero g_cnt, zero flags.
__global__ void init_kernel(const int* __restrict__ w) {
    if (blockIdx.x == 0 && threadIdx.x < 32) {
        int lane = threadIdx.x;
        int v = w[2 * lane + 1];
        unsigned m = __ballot_sync(0xffffffffu, v == 0);
        if (lane == 0) g_is64 = (m == 0xffffffffu) ? 1 : 0;
    }
    if (blockIdx.x == 1 && threadIdx.x < 128) g_flag[threadIdx.x] = 0;
    int i = blockIdx.x * blockDim.x + threadIdx.x;
    if (i < NN / 4) ((int4*)g_cnt)[i] = make_int4(0, 0, 0, 0);
}

// Count in-degrees (dst half of edge_index only) + build fp16 x mirror.
// NE == NN*16 exactly, so the same 1.6M threads cover both jobs.
__global__ void count_x2h_kernel(const void* __restrict__ e,
                                 const float* __restrict__ x) {
    int i = blockIdx.x * blockDim.x + threadIdx.x;
    if (i >= NE) return;
    int d;
    if (g_is64) d = (int)((const long long*)e)[NE + i];
    else        d = ((const int*)e)[NE + i];
    atomicAdd(&g_cnt[d], 1);
    float4 v = __ldg(&((const float4*)x)[i]);
    __half2* dst = (__half2*)g_xh;
    dst[2 * i]     = __floats2half2_rn(v.x, v.y);
    dst[2 * i + 1] = __floats2half2_rn(v.z, v.w);
}

// Single-pass scan with decoupled lookback. 98 blocks x 1024; every block is
// co-resident (98 <= 148 SMs, 1 block/SM), so spinning on peer flags is safe.
__global__ void __launch_bounds__(1024) scan_kernel() {
    __shared__ int s[1024];
    __shared__ int red[128];
    int t = threadIdx.x, b = blockIdx.x;
    int i = b * 1024 + t;
    int v = (i < NN) ? g_cnt[i] : 0;
    s[t] = v;
    __syncthreads();
#pragma unroll
    for (int off = 1; off < 1024; off <<= 1) {
        int tv = (t >= off) ? s[t - off] : 0;
        __syncthreads();
        s[t] += tv;
        __syncthreads();
    }
    if (t == 1023) {                    // publish this block's aggregate
        g_agg[b] = s[1023];
        __threadfence();
        atomicExch(&g_flag[b], 1);
    }
    if (t < 128) {                      // gather aggregates of preceding blocks
        int a = 0;
        if (t < b) {
            while (atomicAdd(&g_flag[t], 0) == 0) { }
            a = g_agg[t];
        }
        red[t] = a;
    }
    __syncthreads();
#pragma unroll
    for (int off = 64; off > 0; off >>= 1) {
        if (t < off) red[t] += red[t + off];
        __syncthreads();
    }
    int prefix = red[0];
    if (i < NN) {
        int rs = prefix + s[t] - v;     // exclusive
        g_rowstart[i] = rs;
        g_cursor[i] = rs;
    }
    if (i == 0) g_rowstart[NN] = NE;
}

// Fill CSR: read edge_index directly, convert inline.
__global__ void __launch_bounds__(256) fill_kernel(const void* __restrict__ e) {
    int i = blockIdx.x * 256 + threadIdx.x;
    if (i >= NE) return;
    int s, d;
    if (g_is64) {
        const long long* p = (const long long*)e;
        s = (int)p[i];
        d = (int)p[NE + i];
    } else {
        const int* p = (const int*)e;
        s = p[i];
        d = p[NE + i];
    }
    int pos = atomicAdd(&g_cursor[d], 1);
    g_csr[pos] = s;
}

// Gather layer 1, warp-per-node: all 32 lanes share one node's degree (zero
// divergence waste). Lane = half2 column; one 128B coalesced row load / edge.
__global__ void __launch_bounds__(256) gather1_kernel() {
    int warp = (blockIdx.x * 256 + threadIdx.x) >> 5;
    int lane = threadIdx.x & 31;
    if (warp >= NN) return;
    int n = warp;
    int beg = __ldg(&g_rowstart[n]), end = __ldg(&g_rowstart[n + 1]);
    const unsigned* xh2 = (const unsigned*)g_xh;   // half2 view: 32 per node row
    float2 acc = make_float2(0.f, 0.f);
    for (int e0 = beg; e0 < end; e0 += 32) {
        int myE = e0 + lane;
        int sv = (myE < end) ? __ldg(&g_csr[myE]) : 0;
        int cnt = min(32, end - e0);
        for (int j = 0; j < cnt; j++) {
            int sj = __shfl_sync(0xffffffffu, sv, j);
            unsigned u = __ldg(&xh2[sj * 32 + lane]);
            float2 f = __half22float2(*(const __half2*)&u);
            acc.x += f.x; acc.y += f.y;
        }
    }
    float inv = 1.f / fmaxf((float)(end - beg), 1.f);
    ((float2*)g_agg1)[n * 32 + lane] = make_float2(acc.x * inv, acc.y * inv);
}

// Fused layer1 + proj, packed f32x2:
//   main: acc_j{aggpart,xpart} += {A,X} * {wl,wr}  -> h = relu(lo+hi+b1)
//   proj: acc_j{p2,r2} += {h,h} * {wl2,wr2}        -> g_p2h (fp16), g_r2 (fp32)
__global__ void __launch_bounds__(256) gemm_fused_kernel(
    const float* __restrict__ x,
    const float* __restrict__ Wl1, const float* __restrict__ Wr1,
    const float* __restrict__ b1,
    const float* __restrict__ Wl2, const float* __restrict__ Wr2) {
    extern __shared__ float smem[];
    float* sW1T = smem;                 // [8][1028]
    float* sWPT = smem + W1T_SZ;        // [8][516]
    float* sAX  = smem + W1T_SZ + WPT_SZ;   // [64][130] float2-interleaved
    float* sH   = sAX;                  // overlay: [64][68] after main loop

    int tid = threadIdx.x;
    for (int i = tid; i < 64 * 64; i += 256) {
        int k = i >> 6, j = i & 63;
        int jt = j >> 3, jj = j & 7;
        sW1T[jt * 1028 + k * 16 + jj * 2 + 0] = Wl1[k * 64 + j];
        sW1T[jt * 1028 + k * 16 + jj * 2 + 1] = Wr1[k * 64 + j];
    }
    for (int i = tid; i < 64 * 32; i += 256) {
        int k = i >> 5, j = i & 31;
        int jtp = j >> 2, jj = j & 3;
        sWPT[jtp * 516 + k * 8 + jj * 2 + 0] = Wl2[k * 32 + j];
        sWPT[jtp * 516 + k * 8 + jj * 2 + 1] = Wr2[k * 32 + j];
    }
    int ln = tid >> 3, jt = tid & 7;    // main: 32 node-pairs x 8 j-groups(8 j each)
    float bb[8];
    {
        float4 ba = __ldg(&((const float4*)b1)[jt * 2]);
        float4 bc = __ldg(&((const float4*)b1)[jt * 2 + 1]);
        bb[0] = ba.x; bb[1] = ba.y; bb[2] = ba.z; bb[3] = ba.w;
        bb[4] = bc.x; bb[5] = bc.y; bb[6] = bc.z; bb[7] = bc.w;
    }
    const float4* agg4 = (const float4*)g_agg1;
    const float4* x4 = (const float4*)x;

    for (int tile = blockIdx.x; tile < NTILES; tile += gridDim.x) {
        int base = tile * TILE_N;
        __syncthreads();
        for (int u = tid; u < 64 * 16; u += 256) {
            int node = u >> 4, c = u & 15;
            int n = base + node;
            float4 a, xv;
            if (n < NN) { a = agg4[n * 16 + c]; xv = x4[n * 16 + c]; }
            else { a = make_float4(0.f,0.f,0.f,0.f); xv = a; }
            float2* dst = (float2*)(sAX + node * 130 + c * 8);
            dst[0] = make_float2(a.x, xv.x);
            dst[1] = make_float2(a.y, xv.y);
            dst[2] = make_float2(a.z, xv.z);
            dst[3] = make_float2(a.w, xv.w);
        }
        __syncthreads();
        {
            const unsigned long long* ax0p = (const unsigned long long*)(sAX + (2 * ln) * 130);
            const unsigned long long* ax1p = (const unsigned long long*)(sAX + (2 * ln + 1) * 130);
            const unsigned long long* wp = (const unsigned long long*)(sW1T + jt * 1028);
            unsigned long long acc0[8], acc1[8];
#pragma unroll
            for (int j = 0; j < 8; j++) { acc0[j] = 0ull; acc1[j] = 0ull; }
#pragma unroll 8
            for (int k = 0; k < 64; k++) {
                unsigned long long ax0 = ax0p[k];
                unsigned long long ax1 = ax1p[k];
                ulonglong2 wA = ((const ulonglong2*)(wp + k * 8))[0];
                ulonglong2 wB = ((const ulonglong2*)(wp + k * 8))[1];
                ulonglong2 wC = ((const ulonglong2*)(wp + k * 8))[2];
                ulonglong2 wD = ((const ulonglong2*)(wp + k * 8))[3];
                acc0[0] = ffma2(ax0, wA.x, acc0[0]); acc1[0] = ffma2(ax1, wA.x, acc1[0]);
                acc0[1] = ffma2(ax0, wA.y, acc0[1]); acc1[1] = ffma2(ax1, wA.y, acc1[1]);
                acc0[2] = ffma2(ax0, wB.x, acc0[2]); acc1[2] = ffma2(ax1, wB.x, acc1[2]);
                acc0[3] = ffma2(ax0, wB.y, acc0[3]); acc1[3] = ffma2(ax1, wB.y, acc1[3]);
                acc0[4] = ffma2(ax0, wC.x, acc0[4]); acc1[4] = ffma2(ax1, wC.x, acc1[4]);
                acc0[5] = ffma2(ax0, wC.y, acc0[5]); acc1[5] = ffma2(ax1, wC.y, acc1[5]);
                acc0[6] = ffma2(ax0, wD.x, acc0[6]); acc1[6] = ffma2(ax1, wD.x, acc1[6]);
                acc0[7] = ffma2(ax0, wD.y, acc0[7]); acc1[7] = ffma2(ax1, wD.y, acc1[7]);
            }
            __syncthreads();
            float h0[8], h1[8];
#pragma unroll
            for (int j = 0; j < 8; j++) {
                float2 f0 = unpack2(acc0[j]);
                float2 f1 = unpack2(acc1[j]);
                h0[j] = fmaxf(f0.x + f0.y + bb[j], 0.f);
                h1[j] = fmaxf(f1.x + f1.y + bb[j], 0.f);
            }
            float4* d0 = (float4*)(sH + (2 * ln) * 68 + jt * 8);
            float4* d1 = (float4*)(sH + (2 * ln + 1) * 68 + jt * 8);
            d0[0] = make_float4(h0[0], h0[1], h0[2], h0[3]);
            d0[1] = make_float4(h0[4], h0[5], h0[6], h0[7]);
            d1[0] = make_float4(h1[0], h1[1], h1[2], h1[3]);
            d1[1] = make_float4(h1[4], h1[5], h1[6], h1[7]);
        }
        __syncthreads();
        {
            const float* h0p = sH + (2 * ln) * 68;
            const float* h1p = sH + (2 * ln + 1) * 68;
            const unsigned long long* wpp = (const unsigned long long*)(sWPT + jt * 516);
            unsigned long long pa0[4], pa1[4];
#pragma unroll
            for (int j = 0; j < 4; j++) { pa0[j] = 0ull; pa1[j] = 0ull; }
#pragma unroll 8
            for (int k = 0; k < 64; k++) {
                float hv0 = h0p[k], hv1 = h1p[k];
                unsigned long long hh0 = pack2(hv0, hv0);
                unsigned long long hh1 = pack2(hv1, hv1);
                ulonglong2 w01 = ((const ulonglong2*)(wpp + k * 4))[0];
                ulonglong2 w23 = ((const ulonglong2*)(wpp + k * 4))[1];
                pa0[0] = ffma2(hh0, w01.x, pa0[0]); pa1[0] = ffma2(hh1, w01.x, pa1[0]);
                pa0[1] = ffma2(hh0, w01.y, pa0[1]); pa1[1] = ffma2(hh1, w01.y, pa1[1]);
                pa0[2] = ffma2(hh0, w23.x, pa0[2]); pa1[2] = ffma2(hh1, w23.x, pa1[2]);
                pa0[3] = ffma2(hh0, w23.y, pa0[3]); pa1[3] = ffma2(hh1, w23.y, pa1[3]);
            }
            int n0 = base + 2 * ln, n1 = n0 + 1;
            float p0[4], r0[4], p1[4], r1[4];
#pragma unroll
            for (int j = 0; j < 4; j++) {
                float2 f0 = unpack2(pa0[j]);
                float2 f1 = unpack2(pa1[j]);
                p0[j] = f0.x; r0[j] = f0.y;
                p1[j] = f1.x; r1[j] = f1.y;
            }
            __half2* p2h = (__half2*)g_p2h;
            if (n0 < NN) {
                p2h[n0 * 16 + jt * 2 + 0] = __floats2half2_rn(p0[0], p0[1]);
                p2h[n0 * 16 + jt * 2 + 1] = __floats2half2_rn(p0[2], p0[3]);
                ((float4*)g_r2)[n0 * 8 + jt] = make_float4(r0[0], r0[1], r0[2], r0[3]);
            }
            if (n1 < NN) {
                p2h[n1 * 16 + jt * 2 + 0] = __floats2half2_rn(p1[0], p1[1]);
                p2h[n1 * 16 + jt * 2 + 1] = __floats2half2_rn(p1[2], p1[3]);
                ((float4*)g_r2)[n1 * 8 + jt] = make_float4(r1[0], r1[1], r1[2], r1[3]);
            }
        }
    }
}

// Final fused, warp-per-node, 2 edges per iteration (half-warp each):
// gather2 (mean of fp16 p2 over neighbors) + root + bias -> out, then trust
// head (32->16 relu -> 16->1 sigmoid) via warp shuffles.
__global__ void __launch_bounds__(256) final_kernel(
    const float* __restrict__ b2, const float* __restrict__ Wt1,
    const float* __restrict__ bt1, const float* __restrict__ Wt2,
    const float* __restrict__ bt2, float* __restrict__ out) {
    __shared__ float sW1[32 * 16], sB2[32], sBt1[16], sW2[16];
    __shared__ float sBt2;
    int tid = threadIdx.x;
    sW1[tid] = Wt1[tid];
    sW1[tid + 256] = Wt1[tid + 256];
    if (tid < 32) sB2[tid] = b2[tid];
    if (tid < 16) { sBt1[tid] = bt1[tid]; sW2[tid] = Wt2[tid]; }
    if (tid == 0) sBt2 = bt2[0];
    __syncthreads();
    int warp = tid >> 5, lane = tid & 31;
    int n = blockIdx.x * 8 + warp;   // 12500 * 8 == 100000 exactly
    int half = lane >> 4, c = lane & 15;   // c = half2 column (dims 2c, 2c+1)
    int beg = __ldg(&g_rowstart[n]), end = __ldg(&g_rowstart[n + 1]);
    const __half2* p2h = (const __half2*)g_p2h;
    float2 acc = make_float2(0.f, 0.f);
    for (int e = beg + half; e < end; e += 2) {
        int s = __ldg(&g_csr[e]);
        float2 f = __half22float2(__ldg(&p2h[s * 16 + c]));
        acc.x += f.x; acc.y += f.y;
    }
    acc.x += __shfl_xor_sync(0xffffffffu, acc.x, 16);
    acc.y += __shfl_xor_sync(0xffffffffu, acc.y, 16);
    float inv = 1.f / fmaxf((float)(end - beg), 1.f);
    float2 r = __ldg(&((const float2*)g_r2)[n * 16 + c]);
    float v0 = acc.x * inv + r.x + sB2[2 * c];
    float v1 = acc.y * inv + r.y + sB2[2 * c + 1];
    if (half == 0) ((float2*)out)[n * 16 + c] = make_float2(v0, v1);
    float a2 = sBt1[c];
#pragma unroll
    for (int j = 0; j < 32; j++) {
        float hv = __shfl_sync(0xffffffffu, (j & 1) ? v1 : v0, j >> 1);
        a2 += hv * sW1[j * 16 + c];
    }
    float t = fmaxf(a2, 0.f) * sW2[c];
    t += __shfl_down_sync(0xffffffffu, t, 8);
    t += __shfl_down_sync(0xffffffffu, t, 4);
    t += __shfl_down_sync(0xffffffffu, t, 2);
    t += __shfl_down_sync(0xffffffffu, t, 1);
    if (lane == 0)
        out[NN * 32 + n] = 1.f / (1.f + __expf(-(t + sBt2)));
}

extern "C" void kernel_launch(void* const* d_in, const int* in_sizes, int n_in,
                              void* d_out, int out_size) {
    const float* x   = (const float*)d_in[0];
    const void*  ei  = d_in[1];
    const float* Wl1 = (const float*)d_in[2];
    const float* Wr1 = (const float*)d_in[3];
    const float* b1  = (const float*)d_in[4];
    const float* Wl2 = (const float*)d_in[5];
    const float* Wr2 = (const float*)d_in[6];
    const float* b2  = (const float*)d_in[7];
    const float* Wt1 = (const float*)d_in[8];
    const float* bt1 = (const float*)d_in[9];
    const float* Wt2 = (const float*)d_in[10];
    const float* bt2 = (const float*)d_in[11];
    float* out = (float*)d_out;

    cudaFuncSetAttribute(gemm_fused_kernel,
                         cudaFuncAttributeMaxDynamicSharedMemorySize, SMEM_BYTES);

    init_kernel<<<98, 256>>>((const int*)ei);
    count_x2h_kernel<<<(NE + 255) / 256, 256>>>(ei, x);
    scan_kernel<<<SCAN_B, 1024>>>();
    fill_kernel<<<(NE + 255) / 256, 256>>>(ei);
    gather1_kernel<<<(NN * 32 + 255) / 256, 256>>>();
    gemm_fused_kernel<<<296, 256, SMEM_BYTES>>>(x, Wl1, Wr1, b1, Wl2, Wr2);
    final_kernel<<<NN / 8, 256>>>(b2, Wt1, bt1, Wt2, bt2, out);
}

// round 14
// speedup vs baseline: 1.0698x; 1.0698x over previous
#include <cuda_runtime.h>
#include <cuda_fp16.h>

#define NN 100000
#define NE 1600000
#define SCAN_B 98           // ceil(100000 / 1024); all 98 blocks co-resident

#define TILE_N 64
#define NTILES ((NN + TILE_N - 1) / TILE_N)   // 1563 (last tile partial)

// smem layout (floats) for fused GEMM kernel
#define W1T_SZ (8 * 1028)   // layer1 weights, 8 jt-regions, {wl,wr} interleaved, +4 pad
#define WPT_SZ (8 * 516)    // proj weights, 8 jtp-regions, {wl2,wr2} interleaved, +4 pad
#define AX_SZ  (64 * 130)   // 64 nodes x 64 k of {agg,x} float2, row 130 floats
#define SMEM_FLOATS (W1T_SZ + WPT_SZ + AX_SZ)
#define SMEM_BYTES  (SMEM_FLOATS * 4)         // 82688 B

// ---- scratch (static __device__ arrays; no allocation allowed) ----
__device__ int    g_is64;
__device__ int    g_cnt[NN];
__device__ int    g_flag[128];     // lookback flags (re-zeroed every launch)
__device__ int    g_agg[128];      // per-block scan aggregates
__device__ int    g_rowstart[NN + 1];
__device__ int    g_cursor[NN];
__device__ int    g_csr[NE];
__device__ __half g_xh[NN * 64];   // fp16 mirror of x (gather path only)
__device__ float  g_agg1[NN * 64];
__device__ __half g_p2h[NN * 32];  // h @ Wl2 in fp16 (gathered in final)
__device__ float  g_r2[NN * 32];   // h @ Wr2 (root term, fp32)

// ---- f32x2 packed helpers ----
__device__ __forceinline__ unsigned long long ffma2(
    unsigned long long a, unsigned long long b, unsigned long long c) {
    unsigned long long d;
    asm("fma.rn.f32x2 %0, %1, %2, %3;" : "=l"(d) : "l"(a), "l"(b), "l"(c));
    return d;
}
__device__ __forceinline__ unsigned long long pack2(float lo, float hi) {
    unsigned long long r;
    asm("mov.b64 %0, {%1, %2};" : "=l"(r) : "f"(lo), "f"(hi));
    return r;
}
__device__ __forceinline__ float2 unpack2(unsigned long long v) {
    float2 f;
    asm("mov.b64 {%0, %1}, %2;" : "=f"(f.x), "=f"(f.y) : "l"(v));
    return f;
}

// init: detect int64 vs int32 edge_index (block 0 warp 0), zero g_cnt, zero flags.
__global__ void init_kernel(const int* __restrict__ w) {
    if (blockIdx.x == 0 && threadIdx.x < 32) {
        int lane = threadIdx.x;
        int v = w[2 * lane + 1];
        unsigned m = __ballot_sync(0xffffffffu, v == 0);
        if (lane == 0) g_is64 = (m == 0xffffffffu) ? 1 : 0;
    }
    if (blockIdx.x == 1 && threadIdx.x < 128) g_flag[threadIdx.x] = 0;
    int i = blockIdx.x * blockDim.x + threadIdx.x;
    if (i < NN / 4) ((int4*)g_cnt)[i] = make_int4(0, 0, 0, 0);
}

// Count in-degrees (dst half of edge_index only) + build fp16 x mirror.
// NE == NN*16 exactly, so the same 1.6M threads cover both jobs.
__global__ void count_x2h_kernel(const void* __restrict__ e,
                                 const float* __restrict__ x) {
    int i = blockIdx.x * blockDim.x + threadIdx.x;
    if (i >= NE) return;
    int d;
    if (g_is64) d = (int)((const long long*)e)[NE + i];
    else        d = ((const int*)e)[NE + i];
    atomicAdd(&g_cnt[d], 1);
    float4 v = __ldg(&((const float4*)x)[i]);
    __half2* dst = (__half2*)g_xh;
    dst[2 * i]     = __floats2half2_rn(v.x, v.y);
    dst[2 * i + 1] = __floats2half2_rn(v.z, v.w);
}

// Single-pass scan with decoupled lookback. 98 blocks x 1024; every block is
// co-resident (98 <= 148 SMs, 1 block/SM), so spinning on peer flags is safe.
__global__ void __launch_bounds__(1024) scan_kernel() {
    __shared__ int s[1024];
    __shared__ int red[128];
    int t = threadIdx.x, b = blockIdx.x;
    int i = b * 1024 + t;
    int v = (i < NN) ? g_cnt[i] : 0;
    s[t] = v;
    __syncthreads();
#pragma unroll
    for (int off = 1; off < 1024; off <<= 1) {
        int tv = (t >= off) ? s[t - off] : 0;
        __syncthreads();
        s[t] += tv;
        __syncthreads();
    }
    if (t == 1023) {                    // publish this block's aggregate
        g_agg[b] = s[1023];
        __threadfence();
        atomicExch(&g_flag[b], 1);
    }
    if (t < 128) {                      // gather aggregates of preceding blocks
        int a = 0;
        if (t < b) {
            while (atomicAdd(&g_flag[t], 0) == 0) { }
            a = g_agg[t];
        }
        red[t] = a;
    }
    __syncthreads();
#pragma unroll
    for (int off = 64; off > 0; off >>= 1) {
        if (t < off) red[t] += red[t + off];
        __syncthreads();
    }
    int prefix = red[0];
    if (i < NN) {
        int rs = prefix + s[t] - v;     // exclusive
        g_rowstart[i] = rs;
        g_cursor[i] = rs;
    }
    if (i == 0) g_rowstart[NN] = NE;
}

// Fill CSR: read edge_index directly, convert inline.
__global__ void __launch_bounds__(256) fill_kernel(const void* __restrict__ e) {
    int i = blockIdx.x * 256 + threadIdx.x;
    if (i >= NE) return;
    int s, d;
    if (g_is64) {
        const long long* p = (const long long*)e;
        s = (int)p[i];
        d = (int)p[NE + i];
    } else {
        const int* p = (const int*)e;
        s = p[i];
        d = p[NE + i];
    }
    int pos = atomicAdd(&g_cursor[d], 1);
    g_csr[pos] = s;
}

// Gather layer 1 (fp16 x mirror): agg1[n] = mean over neighbors of xh[src].
// Thread = (node, 16B chunk of 8 halves); 8 threads/node, unroll-4 -> MLP>=4.
// (R12-proven form; warp-per-node variant regressed: serialized shfl chain.)
__global__ void __launch_bounds__(256) gather1_kernel() {
    int idx = blockIdx.x * 256 + threadIdx.x;
    int n = idx >> 3, c = idx & 7;
    if (n >= NN) return;
    int beg = __ldg(&g_rowstart[n]), end = __ldg(&g_rowstart[n + 1]);
    float acc[8];
#pragma unroll
    for (int j = 0; j < 8; j++) acc[j] = 0.f;
    const uint4* xh4 = (const uint4*)g_xh;   // 8 halves per uint4, 8 per node row
#pragma unroll 4
    for (int e = beg; e < end; e++) {
        int s = __ldg(&g_csr[e]);
        uint4 u = __ldg(&xh4[s * 8 + c]);
        float2 f0 = __half22float2(*(const __half2*)&u.x);
        float2 f1 = __half22float2(*(const __half2*)&u.y);
        float2 f2 = __half22float2(*(const __half2*)&u.z);
        float2 f3 = __half22float2(*(const __half2*)&u.w);
        acc[0] += f0.x; acc[1] += f0.y;
        acc[2] += f1.x; acc[3] += f1.y;
        acc[4] += f2.x; acc[5] += f2.y;
        acc[6] += f3.x; acc[7] += f3.y;
    }
    float inv = 1.f / fmaxf((float)(end - beg), 1.f);
    float4 o0 = make_float4(acc[0] * inv, acc[1] * inv, acc[2] * inv, acc[3] * inv);
    float4 o1 = make_float4(acc[4] * inv, acc[5] * inv, acc[6] * inv, acc[7] * inv);
    ((float4*)g_agg1)[n * 16 + c * 2]     = o0;
    ((float4*)g_agg1)[n * 16 + c * 2 + 1] = o1;
}

// Fused layer1 + proj, packed f32x2:
//   main: acc_j{aggpart,xpart} += {A,X} * {wl,wr}  -> h = relu(lo+hi+b1)
//   proj: acc_j{p2,r2} += {h,h} * {wl2,wr2}        -> g_p2h (fp16), g_r2 (fp32)
__global__ void __launch_bounds__(256) gemm_fused_kernel(
    const float* __restrict__ x,
    const float* __restrict__ Wl1, const float* __restrict__ Wr1,
    const float* __restrict__ b1,
    const float* __restrict__ Wl2, const float* __restrict__ Wr2) {
    extern __shared__ float smem[];
    float* sW1T = smem;                 // [8][1028]
    float* sWPT = smem + W1T_SZ;        // [8][516]
    float* sAX  = smem + W1T_SZ + WPT_SZ;   // [64][130] float2-interleaved
    float* sH   = sAX;                  // overlay: [64][68] after main loop

    int tid = threadIdx.x;
    for (int i = tid; i < 64 * 64; i += 256) {
        int k = i >> 6, j = i & 63;
        int jt = j >> 3, jj = j & 7;
        sW1T[jt * 1028 + k * 16 + jj * 2 + 0] = Wl1[k * 64 + j];
        sW1T[jt * 1028 + k * 16 + jj * 2 + 1] = Wr1[k * 64 + j];
    }
    for (int i = tid; i < 64 * 32; i += 256) {
        int k = i >> 5, j = i & 31;
        int jtp = j >> 2, jj = j & 3;
        sWPT[jtp * 516 + k * 8 + jj * 2 + 0] = Wl2[k * 32 + j];
        sWPT[jtp * 516 + k * 8 + jj * 2 + 1] = Wr2[k * 32 + j];
    }
    int ln = tid >> 3, jt = tid & 7;    // main: 32 node-pairs x 8 j-groups(8 j each)
    float bb[8];
    {
        float4 ba = __ldg(&((const float4*)b1)[jt * 2]);
        float4 bc = __ldg(&((const float4*)b1)[jt * 2 + 1]);
        bb[0] = ba.x; bb[1] = ba.y; bb[2] = ba.z; bb[3] = ba.w;
        bb[4] = bc.x; bb[5] = bc.y; bb[6] = bc.z; bb[7] = bc.w;
    }
    const float4* agg4 = (const float4*)g_agg1;
    const float4* x4 = (const float4*)x;

    for (int tile = blockIdx.x; tile < NTILES; tile += gridDim.x) {
        int base = tile * TILE_N;
        __syncthreads();
        for (int u = tid; u < 64 * 16; u += 256) {
            int node = u >> 4, c = u & 15;
            int n = base + node;
            float4 a, xv;
            if (n < NN) { a = agg4[n * 16 + c]; xv = x4[n * 16 + c]; }
            else { a = make_float4(0.f,0.f,0.f,0.f); xv = a; }
            float2* dst = (float2*)(sAX + node * 130 + c * 8);
            dst[0] = make_float2(a.x, xv.x);
            dst[1] = make_float2(a.y, xv.y);
            dst[2] = make_float2(a.z, xv.z);
            dst[3] = make_float2(a.w, xv.w);
        }
        __syncthreads();
        {
            const unsigned long long* ax0p = (const unsigned long long*)(sAX + (2 * ln) * 130);
            const unsigned long long* ax1p = (const unsigned long long*)(sAX + (2 * ln + 1) * 130);
            const unsigned long long* wp = (const unsigned long long*)(sW1T + jt * 1028);
            unsigned long long acc0[8], acc1[8];
#pragma unroll
            for (int j = 0; j < 8; j++) { acc0[j] = 0ull; acc1[j] = 0ull; }
#pragma unroll 8
            for (int k = 0; k < 64; k++) {
                unsigned long long ax0 = ax0p[k];
                unsigned long long ax1 = ax1p[k];
                ulonglong2 wA = ((const ulonglong2*)(wp + k * 8))[0];
                ulonglong2 wB = ((const ulonglong2*)(wp + k * 8))[1];
                ulonglong2 wC = ((const ulonglong2*)(wp + k * 8))[2];
                ulonglong2 wD = ((const ulonglong2*)(wp + k * 8))[3];
                acc0[0] = ffma2(ax0, wA.x, acc0[0]); acc1[0] = ffma2(ax1, wA.x, acc1[0]);
                acc0[1] = ffma2(ax0, wA.y, acc0[1]); acc1[1] = ffma2(ax1, wA.y, acc1[1]);
                acc0[2] = ffma2(ax0, wB.x, acc0[2]); acc1[2] = ffma2(ax1, wB.x, acc1[2]);
                acc0[3] = ffma2(ax0, wB.y, acc0[3]); acc1[3] = ffma2(ax1, wB.y, acc1[3]);
                acc0[4] = ffma2(ax0, wC.x, acc0[4]); acc1[4] = ffma2(ax1, wC.x, acc1[4]);
                acc0[5] = ffma2(ax0, wC.y, acc0[5]); acc1[5] = ffma2(ax1, wC.y, acc1[5]);
                acc0[6] = ffma2(ax0, wD.x, acc0[6]); acc1[6] = ffma2(ax1, wD.x, acc1[6]);
                acc0[7] = ffma2(ax0, wD.y, acc0[7]); acc1[7] = ffma2(ax1, wD.y, acc1[7]);
            }
            __syncthreads();
            float h0[8], h1[8];
#pragma unroll
            for (int j = 0; j < 8; j++) {
                float2 f0 = unpack2(acc0[j]);
                float2 f1 = unpack2(acc1[j]);
                h0[j] = fmaxf(f0.x + f0.y + bb[j], 0.f);
                h1[j] = fmaxf(f1.x + f1.y + bb[j], 0.f);
            }
            float4* d0 = (float4*)(sH + (2 * ln) * 68 + jt * 8);
            float4* d1 = (float4*)(sH + (2 * ln + 1) * 68 + jt * 8);
            d0[0] = make_float4(h0[0], h0[1], h0[2], h0[3]);
            d0[1] = make_float4(h0[4], h0[5], h0[6], h0[7]);
            d1[0] = make_float4(h1[0], h1[1], h1[2], h1[3]);
            d1[1] = make_float4(h1[4], h1[5], h1[6], h1[7]);
        }
        __syncthreads();
        {
            const float* h0p = sH + (2 * ln) * 68;
            const float* h1p = sH + (2 * ln + 1) * 68;
            const unsigned long long* wpp = (const unsigned long long*)(sWPT + jt * 516);
            unsigned long long pa0[4], pa1[4];
#pragma unroll
            for (int j = 0; j < 4; j++) { pa0[j] = 0ull; pa1[j] = 0ull; }
#pragma unroll 8
            for (int k = 0; k < 64; k++) {
                float hv0 = h0p[k], hv1 = h1p[k];
                unsigned long long hh0 = pack2(hv0, hv0);
                unsigned long long hh1 = pack2(hv1, hv1);
                ulonglong2 w01 = ((const ulonglong2*)(wpp + k * 4))[0];
                ulonglong2 w23 = ((const ulonglong2*)(wpp + k * 4))[1];
                pa0[0] = ffma2(hh0, w01.x, pa0[0]); pa1[0] = ffma2(hh1, w01.x, pa1[0]);
                pa0[1] = ffma2(hh0, w01.y, pa0[1]); pa1[1] = ffma2(hh1, w01.y, pa1[1]);
                pa0[2] = ffma2(hh0, w23.x, pa0[2]); pa1[2] = ffma2(hh1, w23.x, pa1[2]);
                pa0[3] = ffma2(hh0, w23.y, pa0[3]); pa1[3] = ffma2(hh1, w23.y, pa1[3]);
            }
            int n0 = base + 2 * ln, n1 = n0 + 1;
            float p0[4], r0[4], p1[4], r1[4];
#pragma unroll
            for (int j = 0; j < 4; j++) {
                float2 f0 = unpack2(pa0[j]);
                float2 f1 = unpack2(pa1[j]);
                p0[j] = f0.x; r0[j] = f0.y;
                p1[j] = f1.x; r1[j] = f1.y;
            }
            __half2* p2h = (__half2*)g_p2h;
            if (n0 < NN) {
                p2h[n0 * 16 + jt * 2 + 0] = __floats2half2_rn(p0[0], p0[1]);
                p2h[n0 * 16 + jt * 2 + 1] = __floats2half2_rn(p0[2], p0[3]);
                ((float4*)g_r2)[n0 * 8 + jt] = make_float4(r0[0], r0[1], r0[2], r0[3]);
            }
            if (n1 < NN) {
                p2h[n1 * 16 + jt * 2 + 0] = __floats2half2_rn(p1[0], p1[1]);
                p2h[n1 * 16 + jt * 2 + 1] = __floats2half2_rn(p1[2], p1[3]);
                ((float4*)g_r2)[n1 * 8 + jt] = make_float4(r1[0], r1[1], r1[2], r1[3]);
            }
        }
    }
}

// Final fused, warp-per-node, 2 edges per iteration (half-warp each):
// gather2 (mean of fp16 p2 over neighbors) + root + bias -> out, then trust
// head (32->16 relu -> 16->1 sigmoid) via warp shuffles.
__global__ void __launch_bounds__(256) final_kernel(
    const float* __restrict__ b2, const float* __restrict__ Wt1,
    const float* __restrict__ bt1, const float* __restrict__ Wt2,
    const float* __restrict__ bt2, float* __restrict__ out) {
    __shared__ float sW1[32 * 16], sB2[32], sBt1[16], sW2[16];
    __shared__ float sBt2;
    int tid = threadIdx.x;
    sW1[tid] = Wt1[tid];
    sW1[tid + 256] = Wt1[tid + 256];
    if (tid < 32) sB2[tid] = b2[tid];
    if (tid < 16) { sBt1[tid] = bt1[tid]; sW2[tid] = Wt2[tid]; }
    if (tid == 0) sBt2 = bt2[0];
    __syncthreads();
    int warp = tid >> 5, lane = tid & 31;
    int n = blockIdx.x * 8 + warp;   // 12500 * 8 == 100000 exactly
    int half = lane >> 4, c = lane & 15;   // c = half2 column (dims 2c, 2c+1)
    int beg = __ldg(&g_rowstart[n]), end = __ldg(&g_rowstart[n + 1]);
    const __half2* p2h = (const __half2*)g_p2h;
    float2 acc = make_float2(0.f, 0.f);
    for (int e = beg + half; e < end; e += 2) {
        int s = __ldg(&g_csr[e]);
        float2 f = __half22float2(__ldg(&p2h[s * 16 + c]));
        acc.x += f.x; acc.y += f.y;
    }
    acc.x += __shfl_xor_sync(0xffffffffu, acc.x, 16);
    acc.y += __shfl_xor_sync(0xffffffffu, acc.y, 16);
    float inv = 1.f / fmaxf((float)(end - beg), 1.f);
    float2 r = __ldg(&((const float2*)g_r2)[n * 16 + c]);
    float v0 = acc.x * inv + r.x + sB2[2 * c];
    float v1 = acc.y * inv + r.y + sB2[2 * c + 1];
    if (half == 0) ((float2*)out)[n * 16 + c] = make_float2(v0, v1);
    float a2 = sBt1[c];
#pragma unroll
    for (int j = 0; j < 32; j++) {
        float hv = __shfl_sync(0xffffffffu, (j & 1) ? v1 : v0, j >> 1);
        a2 += hv * sW1[j * 16 + c];
    }
    float t = fmaxf(a2, 0.f) * sW2[c];
    t += __shfl_down_sync(0xffffffffu, t, 8);
    t += __shfl_down_sync(0xffffffffu, t, 4);
    t += __shfl_down_sync(0xffffffffu, t, 2);
    t += __shfl_down_sync(0xffffffffu, t, 1);
    if (lane == 0)
        out[NN * 32 + n] = 1.f / (1.f + __expf(-(t + sBt2)));
}

extern "C" void kernel_launch(void* const* d_in, const int* in_sizes, int n_in,
                              void* d_out, int out_size) {
    const float* x   = (const float*)d_in[0];
    const void*  ei  = d_in[1];
    const float* Wl1 = (const float*)d_in[2];
    const float* Wr1 = (const float*)d_in[3];
    const float* b1  = (const float*)d_in[4];
    const float* Wl2 = (const float*)d_in[5];
    const float* Wr2 = (const float*)d_in[6];
    const float* b2  = (const float*)d_in[7];
    const float* Wt1 = (const float*)d_in[8];
    const float* bt1 = (const float*)d_in[9];
    const float* Wt2 = (const float*)d_in[10];
    const float* bt2 = (const float*)d_in[11];
    float* out = (float*)d_out;

    cudaFuncSetAttribute(gemm_fused_kernel,
                         cudaFuncAttributeMaxDynamicSharedMemorySize, SMEM_BYTES);

    init_kernel<<<98, 256>>>((const int*)ei);
    count_x2h_kernel<<<(NE + 255) / 256, 256>>>(ei, x);
    scan_kernel<<<SCAN_B, 1024>>>();
    fill_kernel<<<(NE + 255) / 256, 256>>>(ei);
    gather1_kernel<<<(NN * 8 + 255) / 256, 256>>>();
    gemm_fused_kernel<<<296, 256, SMEM_BYTES>>>(x, Wl1, Wr1, b1, Wl2, Wr2);
    final_kernel<<<NN / 8, 256>>>(b2, Wt1, bt1, Wt2, bt2, out);
}

// round 17
// speedup vs baseline: 1.0730x; 1.0030x over previous
#include <cuda_runtime.h>
#include <cuda_fp16.h>

#define NN 100000
#define NE 1600000
#define SCAN_B 98           // ceil(100000 / 1024); all 98 blocks co-resident

#define TILE_N 64
#define NTILES ((NN + TILE_N - 1) / TILE_N)   // 1563 (last tile partial)

// smem layout (floats) for fused GEMM kernel
#define W1T_SZ (8 * 1028)   // layer1 weights, 8 jt-regions, {wl,wr} interleaved, +4 pad
#define WPT_SZ (8 * 516)    // proj weights, 8 jtp-regions, {wl2,wr2} interleaved, +4 pad
#define AX_SZ  (64 * 130)   // 64 nodes x 64 k of {agg,x} float2, row 130 floats
#define SMEM_FLOATS (W1T_SZ + WPT_SZ + AX_SZ)
#define SMEM_BYTES  (SMEM_FLOATS * 4)         // 82688 B

// ---- scratch (static __device__ arrays; no allocation allowed) ----
__device__ int    g_is64;
__device__ int    g_cnt[NN];
__device__ int    g_flag[128];     // lookback flags (re-zeroed every launch)
__device__ int    g_agg[128];      // per-block scan aggregates
__device__ int    g_rowstart[NN + 1];
__device__ int    g_cursor[NN];
__device__ int    g_csr[NE];
__device__ __half g_xh[NN * 64];   // fp16 mirror of x
__device__ __half g_agg1h[NN * 64];// fp16 neighbor means
__device__ __half g_p2h[NN * 32];  // h @ Wl2 in fp16 (gathered in final)
__device__ float  g_r2[NN * 32];   // h @ Wr2 (root term, fp32)

// ---- f32x2 packed helpers ----
__device__ __forceinline__ unsigned long long ffma2(
    unsigned long long a, unsigned long long b, unsigned long long c) {
    unsigned long long d;
    asm("fma.rn.f32x2 %0, %1, %2, %3;" : "=l"(d) : "l"(a), "l"(b), "l"(c));
    return d;
}
__device__ __forceinline__ unsigned long long pack2(float lo, float hi) {
    unsigned long long r;
    asm("mov.b64 %0, {%1, %2};" : "=l"(r) : "f"(lo), "f"(hi));
    return r;
}
__device__ __forceinline__ float2 unpack2(unsigned long long v) {
    float2 f;
    asm("mov.b64 {%0, %1}, %2;" : "=f"(f.x), "=f"(f.y) : "l"(v));
    return f;
}

// init: detect int64 vs int32 edge_index (block 0 warp 0), zero g_cnt, zero flags.
__global__ void init_kernel(const int* __restrict__ w) {
    if (blockIdx.x == 0 && threadIdx.x < 32) {
        int lane = threadIdx.x;
        int v = w[2 * lane + 1];
        unsigned m = __ballot_sync(0xffffffffu, v == 0);
        if (lane == 0) g_is64 = (m == 0xffffffffu) ? 1 : 0;
    }
    if (blockIdx.x == 1 && threadIdx.x < 128) g_flag[threadIdx.x] = 0;
    int i = blockIdx.x * blockDim.x + threadIdx.x;
    if (i < NN / 4) ((int4*)g_cnt)[i] = make_int4(0, 0, 0, 0);
}

// Count in-degrees (dst half of edge_index only) + build fp16 x mirror.
// NE == NN*16 exactly, so the same 1.6M threads cover both jobs.
__global__ void count_x2h_kernel(const void* __restrict__ e,
                                 const float* __restrict__ x) {
    int i = blockIdx.x * blockDim.x + threadIdx.x;
    if (i >= NE) return;
    int d;
    if (g_is64) d = (int)((const long long*)e)[NE + i];
    else        d = ((const int*)e)[NE + i];
    atomicAdd(&g_cnt[d], 1);
    float4 v = __ldg(&((const float4*)x)[i]);
    __half2* dst = (__half2*)g_xh;
    dst[2 * i]     = __floats2half2_rn(v.x, v.y);
    dst[2 * i + 1] = __floats2half2_rn(v.z, v.w);
}

// Single-pass scan with decoupled lookback. 98 blocks x 1024; every block is
// co-resident (98 <= 148 SMs, 1 block/SM), so spinning on peer flags is safe.
__global__ void __launch_bounds__(1024) scan_kernel() {
    __shared__ int s[1024];
    __shared__ int red[128];
    int t = threadIdx.x, b = blockIdx.x;
    int i = b * 1024 + t;
    int v = (i < NN) ? g_cnt[i] : 0;
    s[t] = v;
    __syncthreads();
#pragma unroll
    for (int off = 1; off < 1024; off <<= 1) {
        int tv = (t >= off) ? s[t - off] : 0;
        __syncthreads();
        s[t] += tv;
        __syncthreads();
    }
    if (t == 1023) {                    // publish this block's aggregate
        g_agg[b] = s[1023];
        __threadfence();
        atomicExch(&g_flag[b], 1);
    }
    if (t < 128) {                      // gather aggregates of preceding blocks
        int a = 0;
        if (t < b) {
            while (atomicAdd(&g_flag[t], 0) == 0) { }
            a = g_agg[t];
        }
        red[t] = a;
    }
    __syncthreads();
#pragma unroll
    for (int off = 64; off > 0; off >>= 1) {
        if (t < off) red[t] += red[t + off];
        __syncthreads();
    }
    int prefix = red[0];
    if (i < NN) {
        int rs = prefix + s[t] - v;     // exclusive
        g_rowstart[i] = rs;
        g_cursor[i] = rs;
    }
    if (i == 0) g_rowstart[NN] = NE;
}

// Fill CSR, 2 edges per thread with 16B vector loads of src/dst pairs.
__global__ void __launch_bounds__(256) fill_kernel(const void* __restrict__ e) {
    int t = blockIdx.x * 256 + threadIdx.x;
    if (t >= NE / 2) return;
    int s0, s1, d0, d1;
    if (g_is64) {
        const ulonglong2* p = (const ulonglong2*)e;
        ulonglong2 sv = __ldg(&p[t]);
        ulonglong2 dv = __ldg(&p[NE / 2 + t]);
        s0 = (int)sv.x; s1 = (int)sv.y;
        d0 = (int)dv.x; d1 = (int)dv.y;
    } else {
        const int2* p = (const int2*)e;
        int2 sv = __ldg(&p[t]);
        int2 dv = __ldg(&p[NE / 2 + t]);
        s0 = sv.x; s1 = sv.y;
        d0 = dv.x; d1 = dv.y;
    }
    int p0 = atomicAdd(&g_cursor[d0], 1);
    int p1 = atomicAdd(&g_cursor[d1], 1);
    g_csr[p0] = s0;
    g_csr[p1] = s1;
}

// Gather layer 1 (fp16 in, fp32 accum, fp16 out): agg1h[n] = mean of xh[src].
// Thread = (node, 16B chunk of 8 halves); 8 threads/node, unroll-4 -> MLP>=4.
__global__ void __launch_bounds__(256) gather1_kernel() {
    int idx = blockIdx.x * 256 + threadIdx.x;
    int n = idx >> 3, c = idx & 7;
    if (n >= NN) return;
    int beg = __ldg(&g_rowstart[n]), end = __ldg(&g_rowstart[n + 1]);
    float acc[8];
#pragma unroll
    for (int j = 0; j < 8; j++) acc[j] = 0.f;
    const uint4* xh4 = (const uint4*)g_xh;   // 8 halves per uint4, 8 per node row
#pragma unroll 4
    for (int e = beg; e < end; e++) {
        int s = __ldg(&g_csr[e]);
        uint4 u = __ldg(&xh4[s * 8 + c]);
        float2 f0 = __half22float2(*(const __half2*)&u.x);
        float2 f1 = __half22float2(*(const __half2*)&u.y);
        float2 f2 = __half22float2(*(const __half2*)&u.z);
        float2 f3 = __half22float2(*(const __half2*)&u.w);
        acc[0] += f0.x; acc[1] += f0.y;
        acc[2] += f1.x; acc[3] += f1.y;
        acc[4] += f2.x; acc[5] += f2.y;
        acc[6] += f3.x; acc[7] += f3.y;
    }
    float inv = 1.f / fmaxf((float)(end - beg), 1.f);
    uint4 o;
    __half2 h01 = __floats2half2_rn(acc[0] * inv, acc[1] * inv);
    __half2 h23 = __floats2half2_rn(acc[2] * inv, acc[3] * inv);
    __half2 h45 = __floats2half2_rn(acc[4] * inv, acc[5] * inv);
    __half2 h67 = __floats2half2_rn(acc[6] * inv, acc[7] * inv);
    o.x = *(const unsigned*)&h01;
    o.y = *(const unsigned*)&h23;
    o.z = *(const unsigned*)&h45;
    o.w = *(const unsigned*)&h67;
    ((uint4*)g_agg1h)[n * 8 + c] = o;
}

// Fused layer1 + proj, packed f32x2 (agg + x both staged from fp16):
//   main: acc_j{aggpart,xpart} += {A,X} * {wl,wr}  -> h = relu(lo+hi+b1)
//   proj: acc_j{p2,r2} += {h,h} * {wl2,wr2}        -> g_p2h (fp16), g_r2 (fp32)
__global__ void __launch_bounds__(256) gemm_fused_kernel(
    const float* __restrict__ Wl1, const float* __restrict__ Wr1,
    const float* __restrict__ b1,
    const float* __restrict__ Wl2, const float* __restrict__ Wr2) {
    extern __shared__ float smem[];
    float* sW1T = smem;                 // [8][1028]
    float* sWPT = smem + W1T_SZ;        // [8][516]
    float* sAX  = smem + W1T_SZ + WPT_SZ;   // [64][130] float2-interleaved
    float* sH   = sAX;                  // overlay: [64][68] after main loop

    int tid = threadIdx.x;
    for (int i = tid; i < 64 * 64; i += 256) {
        int k = i >> 6, j = i & 63;
        int jt = j >> 3, jj = j & 7;
        sW1T[jt * 1028 + k * 16 + jj * 2 + 0] = Wl1[k * 64 + j];
        sW1T[jt * 1028 + k * 16 + jj * 2 + 1] = Wr1[k * 64 + j];
    }
    for (int i = tid; i < 64 * 32; i += 256) {
        int k = i >> 5, j = i & 31;
        int jtp = j >> 2, jj = j & 3;
        sWPT[jtp * 516 + k * 8 + jj * 2 + 0] = Wl2[k * 32 + j];
        sWPT[jtp * 516 + k * 8 + jj * 2 + 1] = Wr2[k * 32 + j];
    }
    int ln = tid >> 3, jt = tid & 7;    // main: 32 node-pairs x 8 j-groups(8 j each)
    float bb[8];
    {
        float4 ba = __ldg(&((const float4*)b1)[jt * 2]);
        float4 bc = __ldg(&((const float4*)b1)[jt * 2 + 1]);
        bb[0] = ba.x; bb[1] = ba.y; bb[2] = ba.z; bb[3] = ba.w;
        bb[4] = bc.x; bb[5] = bc.y; bb[6] = bc.z; bb[7] = bc.w;
    }
    const uint2* aggh = (const uint2*)g_agg1h;   // 4 halves per uint2, 16/row
    const uint2* xh   = (const uint2*)g_xh;

    for (int tile = blockIdx.x; tile < NTILES; tile += gridDim.x) {
        int base = tile * TILE_N;
        __syncthreads();
        for (int u = tid; u < 64 * 16; u += 256) {
            int node = u >> 4, c = u & 15;       // c: k = 4c..4c+3
            int n = base + node;
            float2 a01, a23, x01, x23;
            if (n < NN) {
                uint2 ua = __ldg(&aggh[n * 16 + c]);
                uint2 ux = __ldg(&xh[n * 16 + c]);
                a01 = __half22float2(*(const __half2*)&ua.x);
                a23 = __half22float2(*(const __half2*)&ua.y);
                x01 = __half22float2(*(const __half2*)&ux.x);
                x23 = __half22float2(*(const __half2*)&ux.y);
            } else {
                a01 = a23 = x01 = x23 = make_float2(0.f, 0.f);
            }
            float2* dst = (float2*)(sAX + node * 130 + c * 8);
            dst[0] = make_float2(a01.x, x01.x);
            dst[1] = make_float2(a01.y, x01.y);
            dst[2] = make_float2(a23.x, x23.x);
            dst[3] = make_float2(a23.y, x23.y);
        }
        __syncthreads();
        {
            const unsigned long long* ax0p = (const unsigned long long*)(sAX + (2 * ln) * 130);
            const unsigned long long* ax1p = (const unsigned long long*)(sAX + (2 * ln + 1) * 130);
            const unsigned long long* wp = (const unsigned long long*)(sW1T + jt * 1028);
            unsigned long long acc0[8], acc1[8];
#pragma unroll
            for (int j = 0; j < 8; j++) { acc0[j] = 0ull; acc1[j] = 0ull; }
#pragma unroll 8
            for (int k = 0; k < 64; k++) {
                unsigned long long ax0 = ax0p[k];
                unsigned long long ax1 = ax1p[k];
                ulonglong2 wA = ((const ulonglong2*)(wp + k * 8))[0];
                ulonglong2 wB = ((const ulonglong2*)(wp + k * 8))[1];
                ulonglong2 wC = ((const ulonglong2*)(wp + k * 8))[2];
                ulonglong2 wD = ((const ulonglong2*)(wp + k * 8))[3];
                acc0[0] = ffma2(ax0, wA.x, acc0[0]); acc1[0] = ffma2(ax1, wA.x, acc1[0]);
                acc0[1] = ffma2(ax0, wA.y, acc0[1]); acc1[1] = ffma2(ax1, wA.y, acc1[1]);
                acc0[2] = ffma2(ax0, wB.x, acc0[2]); acc1[2] = ffma2(ax1, wB.x, acc1[2]);
                acc0[3] = ffma2(ax0, wB.y, acc0[3]); acc1[3] = ffma2(ax1, wB.y, acc1[3]);
                acc0[4] = ffma2(ax0, wC.x, acc0[4]); acc1[4] = ffma2(ax1, wC.x, acc1[4]);
                acc0[5] = ffma2(ax0, wC.y, acc0[5]); acc1[5] = ffma2(ax1, wC.y, acc1[5]);
                acc0[6] = ffma2(ax0, wD.x, acc0[6]); acc1[6] = ffma2(ax1, wD.x, acc1[6]);
                acc0[7] = ffma2(ax0, wD.y, acc0[7]); acc1[7] = ffma2(ax1, wD.y, acc1[7]);
            }
            __syncthreads();
            float h0[8], h1[8];
#pragma unroll
            for (int j = 0; j < 8; j++) {
                float2 f0 = unpack2(acc0[j]);
                float2 f1 = unpack2(acc1[j]);
                h0[j] = fmaxf(f0.x + f0.y + bb[j], 0.f);
                h1[j] = fmaxf(f1.x + f1.y + bb[j], 0.f);
            }
            float4* d0 = (float4*)(sH + (2 * ln) * 68 + jt * 8);
            float4* d1 = (float4*)(sH + (2 * ln + 1) * 68 + jt * 8);
            d0[0] = make_float4(h0[0], h0[1], h0[2], h0[3]);
            d0[1] = make_float4(h0[4], h0[5], h0[6], h0[7]);
            d1[0] = make_float4(h1[0], h1[1], h1[2], h1[3]);
            d1[1] = make_float4(h1[4], h1[5], h1[6], h1[7]);
        }
        __syncthreads();
        {
            const float* h0p = sH + (2 * ln) * 68;
            const float* h1p = sH + (2 * ln + 1) * 68;
            const unsigned long long* wpp = (const unsigned long long*)(sWPT + jt * 516);
            unsigned long long pa0[4], pa1[4];
#pragma unroll
            for (int j = 0; j < 4; j++) { pa0[j] = 0ull; pa1[j] = 0ull; }
#pragma unroll 8
            for (int k = 0; k < 64; k++) {
                float hv0 = h0p[k], hv1 = h1p[k];
                unsigned long long hh0 = pack2(hv0, hv0);
                unsigned long long hh1 = pack2(hv1, hv1);
                ulonglong2 w01 = ((const ulonglong2*)(wpp + k * 4))[0];
                ulonglong2 w23 = ((const ulonglong2*)(wpp + k * 4))[1];
                pa0[0] = ffma2(hh0, w01.x, pa0[0]); pa1[0] = ffma2(hh1, w01.x, pa1[0]);
                pa0[1] = ffma2(hh0, w01.y, pa0[1]); pa1[1] = ffma2(hh1, w01.y, pa1[1]);
                pa0[2] = ffma2(hh0, w23.x, pa0[2]); pa1[2] = ffma2(hh1, w23.x, pa1[2]);
                pa0[3] = ffma2(hh0, w23.y, pa0[3]); pa1[3] = ffma2(hh1, w23.y, pa1[3]);
            }
            int n0 = base + 2 * ln, n1 = n0 + 1;
            float p0[4], r0[4], p1[4], r1[4];
#pragma unroll
            for (int j = 0; j < 4; j++) {
                float2 f0 = unpack2(pa0[j]);
                float2 f1 = unpack2(pa1[j]);
                p0[j] = f0.x; r0[j] = f0.y;
                p1[j] = f1.x; r1[j] = f1.y;
            }
            __half2* p2h = (__half2*)g_p2h;
            if (n0 < NN) {
                p2h[n0 * 16 + jt * 2 + 0] = __floats2half2_rn(p0[0], p0[1]);
                p2h[n0 * 16 + jt * 2 + 1] = __floats2half2_rn(p0[2], p0[3]);
                ((float4*)g_r2)[n0 * 8 + jt] = make_float4(r0[0], r0[1], r0[2], r0[3]);
            }
            if (n1 < NN) {
                p2h[n1 * 16 + jt * 2 + 0] = __floats2half2_rn(p1[0], p1[1]);
                p2h[n1 * 16 + jt * 2 + 1] = __floats2half2_rn(p1[2], p1[3]);
                ((float4*)g_r2)[n1 * 8 + jt] = make_float4(r1[0], r1[1], r1[2], r1[3]);
            }
        }
    }
}

// Final fused, warp-per-node, 2 edges per iteration (half-warp each):
// gather2 (mean of fp16 p2 over neighbors) + root + bias -> out, then trust
// head (32->16 relu -> 16->1 sigmoid) via warp shuffles.
__global__ void __launch_bounds__(256) final_kernel(
    const float* __restrict__ b2, const float* __restrict__ Wt1,
    const float* __restrict__ bt1, const float* __restrict__ Wt2,
    const float* __restrict__ bt2, float* __restrict__ out) {
    __shared__ float sW1[32 * 16], sB2[32], sBt1[16], sW2[16];
    __shared__ float sBt2;
    int tid = threadIdx.x;
    sW1[tid] = Wt1[tid];
    sW1[tid + 256] = Wt1[tid + 256];
    if (tid < 32) sB2[tid] = b2[tid];
    if (tid < 16) { sBt1[tid] = bt1[tid]; sW2[tid] = Wt2[tid]; }
    if (tid == 0) sBt2 = bt2[0];
    __syncthreads();
    int warp = tid >> 5, lane = tid & 31;
    int n = blockIdx.x * 8 + warp;   // 12500 * 8 == 100000 exactly
    int half = lane >> 4, c = lane & 15;   // c = half2 column (dims 2c, 2c+1)
    int beg = __ldg(&g_rowstart[n]), end = __ldg(&g_rowstart[n + 1]);
    const __half2* p2h = (const __half2*)g_p2h;
    float2 acc = make_float2(0.f, 0.f);
    for (int e = beg + half; e < end; e += 2) {
        int s = __ldg(&g_csr[e]);
        float2 f = __half22float2(__ldg(&p2h[s * 16 + c]));
        acc.x += f.x; acc.y += f.y;
    }
    acc.x += __shfl_xor_sync(0xffffffffu, acc.x, 16);
    acc.y += __shfl_xor_sync(0xffffffffu, acc.y, 16);
    float inv = 1.f / fmaxf((float)(end - beg), 1.f);
    float2 r = __ldg(&((const float2*)g_r2)[n * 16 + c]);
    float v0 = acc.x * inv + r.x + sB2[2 * c];
    float v1 = acc.y * inv + r.y + sB2[2 * c + 1];
    if (half == 0) ((float2*)out)[n * 16 + c] = make_float2(v0, v1);
    float a2 = sBt1[c];
#pragma unroll
    for (int j = 0; j < 32; j++) {
        float hv = __shfl_sync(0xffffffffu, (j & 1) ? v1 : v0, j >> 1);
        a2 += hv * sW1[j * 16 + c];
    }
    float t = fmaxf(a2, 0.f) * sW2[c];
    t += __shfl_down_sync(0xffffffffu, t, 8);
    t += __shfl_down_sync(0xffffffffu, t, 4);
    t += __shfl_down_sync(0xffffffffu, t, 2);
    t += __shfl_down_sync(0xffffffffu, t, 1);
    if (lane == 0)
        out[NN * 32 + n] = 1.f / (1.f + __expf(-(t + sBt2)));
}

extern "C" void kernel_launch(void* const* d_in, const int* in_sizes, int n_in,
                              void* d_out, int out_size) {
    const float* x   = (const float*)d_in[0];
    const void*  ei  = d_in[1];
    const float* Wl1 = (const float*)d_in[2];
    const float* Wr1 = (const float*)d_in[3];
    const float* b1  = (const float*)d_in[4];
    const float* Wl2 = (const float*)d_in[5];
    const float* Wr2 = (const float*)d_in[6];
    const float* b2  = (const float*)d_in[7];
    const float* Wt1 = (const float*)d_in[8];
    const float* bt1 = (const float*)d_in[9];
    const float* Wt2 = (const float*)d_in[10];
    const float* bt2 = (const float*)d_in[11];
    float* out = (float*)d_out;

    cudaFuncSetAttribute(gemm_fused_kernel,
                         cudaFuncAttributeMaxDynamicSharedMemorySize, SMEM_BYTES);

    init_kernel<<<98, 256>>>((const int*)ei);
    count_x2h_kernel<<<(NE + 255) / 256, 256>>>(ei, x);
    scan_kernel<<<SCAN_B, 1024>>>();
    fill_kernel<<<(NE / 2 + 255) / 256, 256>>>(ei);
    gather1_kernel<<<(NN * 8 + 255) / 256, 256>>>();
    gemm_fused_kernel<<<296, 256, SMEM_BYTES>>>(Wl1, Wr1, b1, Wl2, Wr2);
    final_kernel<<<NN / 8, 256>>>(b2, Wt1, bt1, Wt2, bt2, out);
}